// round 12
// baseline (speedup 1.0000x reference)
#include <cuda_runtime.h>
#include <cstdint>

// ---------------------------------------------------------------------------
// Paillier decryption, CRT-factored via tiny shared-memory lookup tables.
//
//   n = 3599 = 59*61, n^2 = 12,952,801 = 3481 * 3721 (= p^2 * q^2, coprime)
//   lambda = lcm(58,60) = 1740, mu = 1740^{-1} mod 3599 = 1119
//   r = c^1740 mod n^2 via CRT:  r_p = (c mod 3481)^1740 mod 3481,
//   r_q likewise mod 3721; Garner with inv(3481) mod 3721 = 1876 folded into
//   the tables; the unreduced-t / r+k*n^2 slack vanishes mod n (exact).
//   m = (((r + n^2 - 1)/n) * mu) mod n ;  out = relu(float(m)*(inv_scale/1000))
//
// R12: tables are built at COMPILE TIME (constexpr -> __device__ const data in
// the cubin): the setup kernel is gone, the graph is a single launch. Layout
// probe folded into the hot kernel (per-block, negligible). Input loads use
// __ldcg to preserve cross-replay L2 residency (__ldcs evict-first was
// flushing it); output stays __stcs. Hot loop body phase-split so the 16
// random LDS issue back-to-back. Shape: R8's proven optimum (1184x256).
// ---------------------------------------------------------------------------

#define P2 3481u
#define Q2 3721u
#define NN 3599u
#define N2 12952801u
#define MU 1119u
#define INV_P2_MOD_Q2 1876u

// ---- compile-time table generation ----------------------------------------
constexpr uint32_t powmod1740(uint32_t b, uint32_t mod) {
    uint32_t r = 1u, e = 1740u;
    for (int i = 0; i < 11; i++) {
        if (e & 1u) r = (r * b) % mod;
        b = (b * b) % mod;
        e >>= 1u;
    }
    return r;
}

struct Tabs {
    uint32_t P[3481];
    uint16_t A[3721];
};

constexpr Tabs make_tabs() {
    Tabs t{};
    for (uint32_t x = 0; x < 3481u; x++) {
        uint32_t rp = powmod1740(x, P2);
        uint32_t bq = (Q2 - (rp * INV_P2_MOD_Q2) % Q2) % Q2;
        t.P[x] = rp | (bq << 16);
    }
    for (uint32_t y = 0; y < 3721u; y++) {
        t.A[y] = (uint16_t)((powmod1740(y, Q2) * INV_P2_MOD_Q2) % Q2);
    }
    return t;
}

__device__ const Tabs g_tabs = make_tabs();   // constant-initialized, in cubin

// ---- per-element decrypt ---------------------------------------------------
template <bool RELU>
__device__ __forceinline__ float combine(uint32_t pw, uint32_t a, float s) {
    uint32_t t = a + (pw >> 16);           // [0, 7441] — unreduced (exact mod n)
    uint32_t r = (pw & 0xFFFFu) + P2 * t;  // r (+ k*n^2), < 2^26
    uint32_t u = r + (N2 - 1u);
    uint32_t q = u / NN;                   // magic-number division
    uint32_t m = (q * MU) % NN;            // k*n term vanishes mod n
    float f = (float)m * s;
    return RELU ? fmaxf(f, 0.0f) : f;
}

// Load 8 consecutive elements starting at element index o (multiple of 8).
template <int MODE>
__device__ __forceinline__ void load8(const void* in, uint32_t o, uint32_t cv[8]) {
    if (MODE == 1) {                        // int32
        uint4 a = __ldcg((const uint4*)in + (o >> 2));
        uint4 b = __ldcg((const uint4*)in + (o >> 2) + 1);
        cv[0]=a.x; cv[1]=a.y; cv[2]=a.z; cv[3]=a.w;
        cv[4]=b.x; cv[5]=b.y; cv[6]=b.z; cv[7]=b.w;
    } else if (MODE == 2) {                 // float32
        float4 a = __ldcg((const float4*)in + (o >> 2));
        float4 b = __ldcg((const float4*)in + (o >> 2) + 1);
        cv[0]=(uint32_t)a.x; cv[1]=(uint32_t)a.y; cv[2]=(uint32_t)a.z; cv[3]=(uint32_t)a.w;
        cv[4]=(uint32_t)b.x; cv[5]=(uint32_t)b.y; cv[6]=(uint32_t)b.z; cv[7]=(uint32_t)b.w;
    } else if (MODE == 0) {                 // int64 (values < 2^32 -> low words)
        const ulonglong2* p = (const ulonglong2*)in + (o >> 1);
        ulonglong2 a = __ldcg(p), b = __ldcg(p+1), c = __ldcg(p+2), d = __ldcg(p+3);
        cv[0]=(uint32_t)a.x; cv[1]=(uint32_t)a.y; cv[2]=(uint32_t)b.x; cv[3]=(uint32_t)b.y;
        cv[4]=(uint32_t)c.x; cv[5]=(uint32_t)c.y; cv[6]=(uint32_t)d.x; cv[7]=(uint32_t)d.y;
    } else {                                // double (integer-valued < 2^24)
        const double2* p = (const double2*)in + (o >> 1);
        double2 a = __ldcg(p), b = __ldcg(p+1), c = __ldcg(p+2), d = __ldcg(p+3);
        cv[0]=(uint32_t)__double2ll_rn(a.x); cv[1]=(uint32_t)__double2ll_rn(a.y);
        cv[2]=(uint32_t)__double2ll_rn(b.x); cv[3]=(uint32_t)__double2ll_rn(b.y);
        cv[4]=(uint32_t)__double2ll_rn(c.x); cv[5]=(uint32_t)__double2ll_rn(c.y);
        cv[6]=(uint32_t)__double2ll_rn(d.x); cv[7]=(uint32_t)__double2ll_rn(d.y);
    }
}

template <int MODE, bool RELU>
__device__ __forceinline__ void run_loop(const void* in, float* out, uint32_t n,
                                         const uint32_t* sP, const uint16_t* sA,
                                         float s) {
    const uint32_t nocts  = n >> 3;
    const uint32_t stride = gridDim.x * blockDim.x;
    for (uint32_t g = blockIdx.x * blockDim.x + threadIdx.x;
         g < nocts; g += stride) {
        uint32_t o = g << 3;
        uint32_t cv[8];
        load8<MODE>(in, o, cv);

        // Phase A: all indices
        uint32_t xp[8], yq[8];
        #pragma unroll
        for (int j = 0; j < 8; j++) { xp[j] = cv[j] % P2; yq[j] = cv[j] % Q2; }

        // Phase B: 16 LDS back-to-back (replays overlap in the L1 queue)
        uint32_t pw[8], aa[8];
        #pragma unroll
        for (int j = 0; j < 8; j++) pw[j] = sP[xp[j]];
        #pragma unroll
        for (int j = 0; j < 8; j++) aa[j] = (uint32_t)sA[yq[j]];

        // Phase C: combine + store
        float4 lo, hi;
        lo.x = combine<RELU>(pw[0], aa[0], s);
        lo.y = combine<RELU>(pw[1], aa[1], s);
        lo.z = combine<RELU>(pw[2], aa[2], s);
        lo.w = combine<RELU>(pw[3], aa[3], s);
        hi.x = combine<RELU>(pw[4], aa[4], s);
        hi.y = combine<RELU>(pw[5], aa[5], s);
        hi.z = combine<RELU>(pw[6], aa[6], s);
        hi.w = combine<RELU>(pw[7], aa[7], s);
        __stcs((float4*)out + (o >> 2),     lo);
        __stcs((float4*)out + (o >> 2) + 1, hi);
    }
    // Scalar tail (n % 8 != 0)
    uint32_t tail = nocts << 3;
    uint32_t ti = tail + blockIdx.x * blockDim.x + threadIdx.x;
    if (blockIdx.x == 0 && ti < n) {
        uint32_t cv;
        if (MODE == 0)      cv = (uint32_t)((const unsigned long long*)in)[ti];
        else if (MODE == 1) cv = ((const uint32_t*)in)[ti];
        else if (MODE == 2) cv = (uint32_t)((const float*)in)[ti];
        else                cv = (uint32_t)((const double*)in)[ti];
        out[ti] = combine<RELU>(sP[cv % P2], (uint32_t)sA[cv % Q2], s);
    }
}

template <int MODE>
__device__ __forceinline__ void dispatch_relu(const void* in, float* out, uint32_t n,
                                              const uint32_t* sP, const uint16_t* sA,
                                              float s) {
    if (s >= 0.0f) run_loop<MODE, false>(in, out, n, sP, sA, s);
    else           run_loop<MODE, true >(in, out, n, sP, sA, s);
}

__global__ __launch_bounds__(256) void paillier_dec_kernel(
    const void* __restrict__ in,
    const float* __restrict__ inv_scale,
    float* __restrict__ out,
    uint32_t n)
{
    __shared__ uint32_t sP[3481];
    __shared__ uint16_t sA[3721];
    __shared__ int sMode;

    // Stage compile-time tables from global (L2-resident after first block).
    for (int i = threadIdx.x; i < 3481; i += 256) sP[i] = g_tabs.P[i];
    for (int i = threadIdx.x; i < 3721; i += 256) sA[i] = g_tabs.A[i];

    // Layout probe from the first 64 words (thread 0; cheap, deterministic).
    if (threadIdx.x == 0) {
        const uint32_t* w = (const uint32_t*)in;
        bool odd_zero = true, all_small = true, dbl_exp = true, even_low29 = true;
        #pragma unroll
        for (int k = 0; k < 64; k++) {
            uint32_t v = __ldg(w + k);
            if (k & 1) {
                if (v != 0u) odd_zero = false;
                uint32_t e = (v >> 20) & 0x7FFu;
                if (e < 0x3FFu || e > 0x416u) dbl_exp = false;
            } else {
                if (v & 0x1FFFFFFFu) even_low29 = false;
            }
            if (v >= 0x01000000u) all_small = false;
        }
        int mode;
        if (odd_zero)                   mode = 0;   // int64
        else if (all_small)             mode = 1;   // int32
        else if (dbl_exp && even_low29) mode = 3;   // double
        else                            mode = 2;   // float32
        sMode = mode;
    }
    __syncthreads();

    const float s = inv_scale[0] / 1000.0f;
    switch (sMode) {                       // uniform per block
        case 0: dispatch_relu<0>(in, out, n, sP, sA, s); break;
        case 1: dispatch_relu<1>(in, out, n, sP, sA, s); break;
        case 2: dispatch_relu<2>(in, out, n, sP, sA, s); break;
        default: dispatch_relu<3>(in, out, n, sP, sA, s); break;
    }
}

extern "C" void kernel_launch(void* const* d_in, const int* in_sizes, int n_in,
                              void* d_out, int out_size) {
    // Identify inputs by size: ciphertext tensor is huge, inv_scale is 1 elem.
    int ci = 0, si = 1;
    if (n_in >= 2 && in_sizes[0] <= 1) { ci = 1; si = 0; }
    const void* c        = d_in[ci];
    const float* inv_scl = (const float*)d_in[si];
    float* out           = (float*)d_out;
    uint32_t n = (uint32_t)out_size;   // output element count is unambiguous

    // Single launch: tables live in the cubin, probe is in-kernel.
    // Persistent single wave: 148 SMs x 8 blocks x 256 threads (R8 shape).
    paillier_dec_kernel<<<148 * 8, 256>>>(c, inv_scl, out, n);
}

// round 13
// speedup vs baseline: 1.0428x; 1.0428x over previous
#include <cuda_runtime.h>
#include <cstdint>

// ---------------------------------------------------------------------------
// Paillier decryption, CRT-factored via tiny shared-memory lookup tables.
//
//   n = 3599 = 59*61, n^2 = 12,952,801 = 3481 * 3721 (= p^2 * q^2, coprime)
//   lambda = lcm(58,60) = 1740, mu = 1740^{-1} mod 3599 = 1119
//   r = c^1740 mod n^2 via CRT:  r_p = (c mod 3481)^1740 mod 3481,
//   r_q likewise mod 3721; Garner with inv(3481) mod 3721 = 1876 folded into
//   the tables; the unreduced-t / r+k*n^2 slack vanishes mod n (exact).
//   m = (((r + n^2 - 1)/n) * mu) mod n ;  out = relu(float(m)*(inv_scale/1000))
//
// R13 = R12's structure (compile-time tables in the cubin -> single-launch
// graph, in-kernel layout probe) + R11's exact hot-loop body (interleaved
// dec_one; R12's phase-split blew regs 32->64 and halved occupancy) +
// __launch_bounds__(256, 8) to pin 32 regs / 8 blocks/SM.
// ---------------------------------------------------------------------------

#define P2 3481u
#define Q2 3721u
#define NN 3599u
#define N2 12952801u
#define MU 1119u
#define INV_P2_MOD_Q2 1876u

// ---- compile-time table generation ----------------------------------------
constexpr uint32_t powmod1740(uint32_t b, uint32_t mod) {
    uint32_t r = 1u, e = 1740u;
    for (int i = 0; i < 11; i++) {
        if (e & 1u) r = (r * b) % mod;
        b = (b * b) % mod;
        e >>= 1u;
    }
    return r;
}

struct Tabs {
    uint32_t P[3481];
    uint16_t A[3721];
};

constexpr Tabs make_tabs() {
    Tabs t{};
    for (uint32_t x = 0; x < 3481u; x++) {
        uint32_t rp = powmod1740(x, P2);
        uint32_t bq = (Q2 - (rp * INV_P2_MOD_Q2) % Q2) % Q2;
        t.P[x] = rp | (bq << 16);
    }
    for (uint32_t y = 0; y < 3721u; y++) {
        t.A[y] = (uint16_t)((powmod1740(y, Q2) * INV_P2_MOD_Q2) % Q2);
    }
    return t;
}

__device__ const Tabs g_tabs = make_tabs();   // constant-initialized, in cubin

// ---- per-element decrypt (R11 form) ----------------------------------------
template <bool RELU>
__device__ __forceinline__ float dec_one(uint32_t cv, const uint32_t* sP,
                                         const uint16_t* sA, float s) {
    uint32_t xp = cv % P2;
    uint32_t yq = cv % Q2;
    uint32_t pw = sP[xp];
    uint32_t a  = (uint32_t)sA[yq];
    uint32_t t  = a + (pw >> 16);          // [0, 7441] — unreduced (exact mod n)
    uint32_t r  = (pw & 0xFFFFu) + P2 * t; // r (+ k*n^2), < 2^26
    uint32_t u  = r + (N2 - 1u);
    uint32_t q  = u / NN;                  // magic-number division
    uint32_t m  = (q * MU) % NN;           // k*n term vanishes mod n
    float f = (float)m * s;
    return RELU ? fmaxf(f, 0.0f) : f;      // m>=0, so s>=0 -> relu is identity
}

// Load 8 consecutive elements starting at element index o (multiple of 8).
template <int MODE>
__device__ __forceinline__ void load8(const void* in, uint32_t o, uint32_t cv[8]) {
    if (MODE == 1) {                        // int32
        uint4 a = __ldcg((const uint4*)in + (o >> 2));
        uint4 b = __ldcg((const uint4*)in + (o >> 2) + 1);
        cv[0]=a.x; cv[1]=a.y; cv[2]=a.z; cv[3]=a.w;
        cv[4]=b.x; cv[5]=b.y; cv[6]=b.z; cv[7]=b.w;
    } else if (MODE == 2) {                 // float32
        float4 a = __ldcg((const float4*)in + (o >> 2));
        float4 b = __ldcg((const float4*)in + (o >> 2) + 1);
        cv[0]=(uint32_t)a.x; cv[1]=(uint32_t)a.y; cv[2]=(uint32_t)a.z; cv[3]=(uint32_t)a.w;
        cv[4]=(uint32_t)b.x; cv[5]=(uint32_t)b.y; cv[6]=(uint32_t)b.z; cv[7]=(uint32_t)b.w;
    } else if (MODE == 0) {                 // int64 (values < 2^32 -> low words)
        const ulonglong2* p = (const ulonglong2*)in + (o >> 1);
        ulonglong2 a = __ldcg(p), b = __ldcg(p+1), c = __ldcg(p+2), d = __ldcg(p+3);
        cv[0]=(uint32_t)a.x; cv[1]=(uint32_t)a.y; cv[2]=(uint32_t)b.x; cv[3]=(uint32_t)b.y;
        cv[4]=(uint32_t)c.x; cv[5]=(uint32_t)c.y; cv[6]=(uint32_t)d.x; cv[7]=(uint32_t)d.y;
    } else {                                // double (integer-valued < 2^24)
        const double2* p = (const double2*)in + (o >> 1);
        double2 a = __ldcg(p), b = __ldcg(p+1), c = __ldcg(p+2), d = __ldcg(p+3);
        cv[0]=(uint32_t)__double2ll_rn(a.x); cv[1]=(uint32_t)__double2ll_rn(a.y);
        cv[2]=(uint32_t)__double2ll_rn(b.x); cv[3]=(uint32_t)__double2ll_rn(b.y);
        cv[4]=(uint32_t)__double2ll_rn(c.x); cv[5]=(uint32_t)__double2ll_rn(c.y);
        cv[6]=(uint32_t)__double2ll_rn(d.x); cv[7]=(uint32_t)__double2ll_rn(d.y);
    }
}

template <int MODE, bool RELU>
__device__ __forceinline__ void run_loop(const void* in, float* out, uint32_t n,
                                         const uint32_t* sP, const uint16_t* sA,
                                         float s) {
    const uint32_t nocts  = n >> 3;
    const uint32_t stride = gridDim.x * blockDim.x;
    for (uint32_t g = blockIdx.x * blockDim.x + threadIdx.x;
         g < nocts; g += stride) {
        uint32_t o = g << 3;
        uint32_t cv[8];
        load8<MODE>(in, o, cv);
        float4 lo, hi;
        lo.x = dec_one<RELU>(cv[0], sP, sA, s);
        lo.y = dec_one<RELU>(cv[1], sP, sA, s);
        lo.z = dec_one<RELU>(cv[2], sP, sA, s);
        lo.w = dec_one<RELU>(cv[3], sP, sA, s);
        hi.x = dec_one<RELU>(cv[4], sP, sA, s);
        hi.y = dec_one<RELU>(cv[5], sP, sA, s);
        hi.z = dec_one<RELU>(cv[6], sP, sA, s);
        hi.w = dec_one<RELU>(cv[7], sP, sA, s);
        __stcs((float4*)out + (o >> 2),     lo);
        __stcs((float4*)out + (o >> 2) + 1, hi);
    }
    // Scalar tail (n % 8 != 0)
    uint32_t tail = nocts << 3;
    uint32_t ti = tail + blockIdx.x * blockDim.x + threadIdx.x;
    if (blockIdx.x == 0 && ti < n) {
        uint32_t cv;
        if (MODE == 0)      cv = (uint32_t)((const unsigned long long*)in)[ti];
        else if (MODE == 1) cv = ((const uint32_t*)in)[ti];
        else if (MODE == 2) cv = (uint32_t)((const float*)in)[ti];
        else                cv = (uint32_t)((const double*)in)[ti];
        out[ti] = dec_one<RELU>(cv, sP, sA, s);
    }
}

template <int MODE>
__device__ __forceinline__ void dispatch_relu(const void* in, float* out, uint32_t n,
                                              const uint32_t* sP, const uint16_t* sA,
                                              float s) {
    if (s >= 0.0f) run_loop<MODE, false>(in, out, n, sP, sA, s);
    else           run_loop<MODE, true >(in, out, n, sP, sA, s);
}

__global__ __launch_bounds__(256, 8) void paillier_dec_kernel(
    const void* __restrict__ in,
    const float* __restrict__ inv_scale,
    float* __restrict__ out,
    uint32_t n)
{
    __shared__ uint32_t sP[3481];
    __shared__ uint16_t sA[3721];
    __shared__ int sMode;

    // Stage compile-time tables from global (L2-resident after first blocks).
    for (int i = threadIdx.x; i < 3481; i += 256) sP[i] = g_tabs.P[i];
    for (int i = threadIdx.x; i < 3721; i += 256) sA[i] = g_tabs.A[i];

    // Layout probe from the first 64 words (thread 0; cheap, deterministic).
    if (threadIdx.x == 0) {
        const uint32_t* w = (const uint32_t*)in;
        bool odd_zero = true, all_small = true, dbl_exp = true, even_low29 = true;
        #pragma unroll
        for (int k = 0; k < 64; k++) {
            uint32_t v = __ldg(w + k);
            if (k & 1) {
                if (v != 0u) odd_zero = false;
                uint32_t e = (v >> 20) & 0x7FFu;
                if (e < 0x3FFu || e > 0x416u) dbl_exp = false;
            } else {
                if (v & 0x1FFFFFFFu) even_low29 = false;
            }
            if (v >= 0x01000000u) all_small = false;
        }
        int mode;
        if (odd_zero)                   mode = 0;   // int64
        else if (all_small)             mode = 1;   // int32
        else if (dbl_exp && even_low29) mode = 3;   // double
        else                            mode = 2;   // float32
        sMode = mode;
    }
    __syncthreads();

    const float s = inv_scale[0] / 1000.0f;
    switch (sMode) {                       // uniform per block
        case 0: dispatch_relu<0>(in, out, n, sP, sA, s); break;
        case 1: dispatch_relu<1>(in, out, n, sP, sA, s); break;
        case 2: dispatch_relu<2>(in, out, n, sP, sA, s); break;
        default: dispatch_relu<3>(in, out, n, sP, sA, s); break;
    }
}

extern "C" void kernel_launch(void* const* d_in, const int* in_sizes, int n_in,
                              void* d_out, int out_size) {
    // Identify inputs by size: ciphertext tensor is huge, inv_scale is 1 elem.
    int ci = 0, si = 1;
    if (n_in >= 2 && in_sizes[0] <= 1) { ci = 1; si = 0; }
    const void* c        = d_in[ci];
    const float* inv_scl = (const float*)d_in[si];
    float* out           = (float*)d_out;
    uint32_t n = (uint32_t)out_size;   // output element count is unambiguous

    // Single launch: tables live in the cubin, probe is in-kernel.
    // Persistent single wave: 148 SMs x 8 blocks x 256 threads (R8 shape).
    paillier_dec_kernel<<<148 * 8, 256>>>(c, inv_scl, out, n);
}

// round 14
// speedup vs baseline: 1.1550x; 1.1076x over previous
#include <cuda_runtime.h>
#include <cstdint>

// ---------------------------------------------------------------------------
// Paillier decryption, CRT-factored via tiny shared-memory lookup tables.
//
//   n = 3599 = 59*61, n^2 = 12,952,801 = 3481 * 3721 (= p^2 * q^2, coprime)
//   lambda = lcm(58,60) = 1740, mu = 1740^{-1} mod 3599 = 1119
//   r = c^1740 mod n^2 via CRT:  r_p = (c mod 3481)^1740 mod 3481,
//   r_q likewise mod 3721; Garner: t=(r_q-r_p)*inv(3481) mod 3721 (inv=1876),
//   r = r_p + 3481*t.
//   m = (floor((r-1)/n) * mu) mod n = (((r + n^2 - 1)/n) * mu) mod n
//   out = relu( float(m) * (inv_scale / 1000) )
//
// R14 = R8 verbatim (measured best, 61.6us). Converged configuration:
//  - setup kernel builds tables + probes layout once (graph pipelines it at
//    ~zero wall cost; in-kernel build/probe variants measured worse)
//  - hot kernel: 1184 blocks x 256 thr, single persistent wave, 32 regs
//    (= exactly the 64-warp regfile limit: 32*256*8 = 64K)
//  - 8 elems/thread/iter, __ldcs input / __stcs output (both measured best)
//  - 2 random LDS lookups/elem is the information floor for this CRT split;
//    plateau is regfile-occupancy x LDS-queue latency (~62us).
// ---------------------------------------------------------------------------

#define P2 3481u
#define Q2 3721u
#define NN 3599u
#define N2 12952801u
#define MU 1119u
#define INV_P2_MOD_Q2 1876u

__device__ uint32_t g_Ptab[3481];
__device__ uint16_t g_Atab[3721];
__device__ int g_mode;   // 0=int64, 1=int32, 2=float32, 3=double

template <uint32_t MOD>
__device__ __forceinline__ uint32_t powmod_lambda(uint32_t b) {
    // exponent 1740 = 0b11011001100 (11 bits); all products < 3721^2 < 2^24
    uint32_t r = 1u;
    uint32_t e = 1740u;
    #pragma unroll
    for (int i = 0; i < 11; i++) {
        if (e & 1u) r = (r * b) % MOD;
        b = (b * b) % MOD;
        e >>= 1u;
    }
    return r;
}

__global__ void setup_kernel(const uint32_t* __restrict__ w) {
    int i = blockIdx.x * blockDim.x + threadIdx.x;
    if (i < 3481) {
        uint32_t rp = powmod_lambda<P2>((uint32_t)i);
        uint32_t bq = (Q2 - (rp * INV_P2_MOD_Q2) % Q2) % Q2;
        g_Ptab[i] = rp | (bq << 16);
    } else if (i < 3481 + 3721) {
        uint32_t y  = (uint32_t)(i - 3481);
        uint32_t aq = (powmod_lambda<Q2>(y) * INV_P2_MOD_Q2) % Q2;
        g_Atab[y] = (uint16_t)aq;
    } else if (i == 3481 + 3721) {
        // Layout probe: classify the input buffer's element encoding.
        bool odd_zero   = true;   // int64: high halves all 0
        bool all_small  = true;   // int32: every word < 2^24
        bool dbl_exp    = true;   // double: hi-word exponent in [0x3FF,0x416]
        bool even_low29 = true;   // double: integer<2^24 -> low 29 bits clear
        #pragma unroll
        for (int k = 0; k < 64; k++) {
            uint32_t v = w[k];
            if (k & 1) {
                if (v != 0u) odd_zero = false;
                uint32_t e = (v >> 20) & 0x7FFu;
                if (e < 0x3FFu || e > 0x416u) dbl_exp = false;
            } else {
                if (v & 0x1FFFFFFFu) even_low29 = false;
            }
            if (v >= 0x01000000u) all_small = false;
        }
        int mode;
        if (odd_zero)                   mode = 0;   // int64
        else if (all_small)             mode = 1;   // int32
        else if (dbl_exp && even_low29) mode = 3;   // double
        else                            mode = 2;   // float32
        g_mode = mode;
    }
}

__device__ __forceinline__ float dec_one(uint32_t cv, const uint32_t* sP,
                                         const uint16_t* sA, float s) {
    uint32_t xp = cv % P2;
    uint32_t yq = cv % Q2;
    uint32_t pw = sP[xp];
    uint32_t a  = (uint32_t)sA[yq];
    uint32_t rp = pw & 0xFFFFu;
    uint32_t t  = a + (pw >> 16);          // < 2*Q2
    t = umin(t, t - Q2);                   // branchless cond-sub
    uint32_t r = rp + P2 * t;              // r = c^lambda mod n^2, < n^2
    uint32_t u = r + (N2 - 1u);            // < 2^25
    uint32_t q = u / NN;                   // magic-number division
    uint32_t m = (q * MU) % NN;            // q*MU < 2^23
    return fmaxf((float)m * s, 0.0f);
}

// Load 8 consecutive elements starting at element index o (multiple of 8).
template <int MODE>
__device__ __forceinline__ void load8(const void* in, uint32_t o, uint32_t cv[8]) {
    if (MODE == 1) {                        // int32
        uint4 a = __ldcs((const uint4*)in + (o >> 2));
        uint4 b = __ldcs((const uint4*)in + (o >> 2) + 1);
        cv[0]=a.x; cv[1]=a.y; cv[2]=a.z; cv[3]=a.w;
        cv[4]=b.x; cv[5]=b.y; cv[6]=b.z; cv[7]=b.w;
    } else if (MODE == 2) {                 // float32
        float4 a = __ldcs((const float4*)in + (o >> 2));
        float4 b = __ldcs((const float4*)in + (o >> 2) + 1);
        cv[0]=(uint32_t)a.x; cv[1]=(uint32_t)a.y; cv[2]=(uint32_t)a.z; cv[3]=(uint32_t)a.w;
        cv[4]=(uint32_t)b.x; cv[5]=(uint32_t)b.y; cv[6]=(uint32_t)b.z; cv[7]=(uint32_t)b.w;
    } else if (MODE == 0) {                 // int64 (values < 2^32 -> low words)
        const ulonglong2* p = (const ulonglong2*)in + (o >> 1);
        ulonglong2 a = __ldcs(p), b = __ldcs(p+1), c = __ldcs(p+2), d = __ldcs(p+3);
        cv[0]=(uint32_t)a.x; cv[1]=(uint32_t)a.y; cv[2]=(uint32_t)b.x; cv[3]=(uint32_t)b.y;
        cv[4]=(uint32_t)c.x; cv[5]=(uint32_t)c.y; cv[6]=(uint32_t)d.x; cv[7]=(uint32_t)d.y;
    } else {                                // double (integer-valued < 2^24)
        const double2* p = (const double2*)in + (o >> 1);
        double2 a = __ldcs(p), b = __ldcs(p+1), c = __ldcs(p+2), d = __ldcs(p+3);
        cv[0]=(uint32_t)__double2ll_rn(a.x); cv[1]=(uint32_t)__double2ll_rn(a.y);
        cv[2]=(uint32_t)__double2ll_rn(b.x); cv[3]=(uint32_t)__double2ll_rn(b.y);
        cv[4]=(uint32_t)__double2ll_rn(c.x); cv[5]=(uint32_t)__double2ll_rn(c.y);
        cv[6]=(uint32_t)__double2ll_rn(d.x); cv[7]=(uint32_t)__double2ll_rn(d.y);
    }
}

template <int MODE>
__device__ __forceinline__ void run_loop(const void* in, float* out, uint32_t n,
                                         const uint32_t* sP, const uint16_t* sA,
                                         float s) {
    const uint32_t nocts  = n >> 3;
    const uint32_t stride = gridDim.x * blockDim.x;
    for (uint32_t g = blockIdx.x * blockDim.x + threadIdx.x;
         g < nocts; g += stride) {
        uint32_t o = g << 3;
        uint32_t cv[8];
        load8<MODE>(in, o, cv);
        float4 lo, hi;
        lo.x = dec_one(cv[0], sP, sA, s);
        lo.y = dec_one(cv[1], sP, sA, s);
        lo.z = dec_one(cv[2], sP, sA, s);
        lo.w = dec_one(cv[3], sP, sA, s);
        hi.x = dec_one(cv[4], sP, sA, s);
        hi.y = dec_one(cv[5], sP, sA, s);
        hi.z = dec_one(cv[6], sP, sA, s);
        hi.w = dec_one(cv[7], sP, sA, s);
        __stcs((float4*)out + (o >> 2),     lo);
        __stcs((float4*)out + (o >> 2) + 1, hi);
    }
    // Scalar tail (n % 8 != 0)
    uint32_t tail = nocts << 3;
    uint32_t ti = tail + blockIdx.x * blockDim.x + threadIdx.x;
    if (blockIdx.x == 0 && ti < n) {
        uint32_t cv;
        if (MODE == 0)      cv = (uint32_t)((const unsigned long long*)in)[ti];
        else if (MODE == 1) cv = ((const uint32_t*)in)[ti];
        else if (MODE == 2) cv = (uint32_t)((const float*)in)[ti];
        else                cv = (uint32_t)((const double*)in)[ti];
        out[ti] = dec_one(cv, sP, sA, s);
    }
}

__global__ __launch_bounds__(256) void paillier_dec_kernel(
    const void* __restrict__ in,
    const float* __restrict__ inv_scale,
    float* __restrict__ out,
    uint32_t n)
{
    __shared__ uint32_t sP[3481];
    __shared__ uint16_t sA[3721];
    for (int i = threadIdx.x; i < 3481; i += 256) sP[i] = g_Ptab[i];
    for (int i = threadIdx.x; i < 3721; i += 256) sA[i] = g_Atab[i];
    __syncthreads();

    const float s = inv_scale[0] / 1000.0f;
    switch (g_mode) {                      // uniform across the grid
        case 0: run_loop<0>(in, out, n, sP, sA, s); break;
        case 1: run_loop<1>(in, out, n, sP, sA, s); break;
        case 2: run_loop<2>(in, out, n, sP, sA, s); break;
        default: run_loop<3>(in, out, n, sP, sA, s); break;
    }
}

extern "C" void kernel_launch(void* const* d_in, const int* in_sizes, int n_in,
                              void* d_out, int out_size) {
    // Identify inputs by size: ciphertext tensor is huge, inv_scale is 1 elem.
    int ci = 0, si = 1;
    if (n_in >= 2 && in_sizes[0] <= 1) { ci = 1; si = 0; }
    const void* c        = d_in[ci];
    const float* inv_scl = (const float*)d_in[si];
    float* out           = (float*)d_out;
    uint32_t n = (uint32_t)out_size;   // output element count is unambiguous

    setup_kernel<<<(3481 + 3721 + 1 + 255) / 256, 256>>>((const uint32_t*)c);

    // Persistent: 148 SMs x 8 blocks x 256 threads (64 warps/SM, 32 regs =
    // exactly the regfile limit for full occupancy).
    paillier_dec_kernel<<<148 * 8, 256>>>(c, inv_scl, out, n);
}

// round 15
// speedup vs baseline: 1.1670x; 1.0104x over previous
#include <cuda_runtime.h>
#include <cstdint>

// ---------------------------------------------------------------------------
// Paillier decryption, CRT-factored via tiny shared-memory lookup tables.
//
//   n = 3599 = 59*61, n^2 = 12,952,801 = 3481 * 3721 (= p^2 * q^2, coprime)
//   lambda = lcm(58,60) = 1740, mu = 1740^{-1} mod 3599 = 1119
//   r = c^1740 mod n^2 via CRT:  r_p = (c mod 3481)^1740 mod 3481,
//   r_q likewise mod 3721. Garner with inv(3481) mod 3721 = 1876 folded into
//   the tables:
//     Atab[y]   = (y^1740 mod 3721)*1876 mod 3721            (a)
//     Ptab[x]   = r_p + 3481*((3721 - r_p*1876 mod 3721) mod 3721)   (pc)
//   then r' = pc + 3481*a = r + k*n^2 with k in {0,1,2} (t unreduced).
//   m = (((r' + n^2 - 1)/n) * mu) mod n:  u < 3n^2 < 2^26 (exact udiv), and
//   the k*n^2 slack becomes k*n in the quotient, vanishing mod n after *mu.
//   out = relu( float(m) * (inv_scale / 1000) ); m >= 0 so relu is identity
//   whenever the uniform scale s >= 0 (templated out).
//
// R15 (final): converged configuration, locked by 12 rounds of A/B:
//  - setup kernel builds tables + probes input layout once (graph pipelines
//    it at zero wall cost; fused in-kernel build measured +22us)
//  - hot kernel: 1184 blocks x 256 thr, single persistent wave, 32 regs
//    (= exactly the 64-warp/SM regfile limit; every other shape lost)
//  - 8 elems/thread/iter, __ldcs input / __stcs output (measured best)
//  - 2 random LDS lookups/elem = information floor for this CRT split;
//    plateau is LDS-conflict latency (~62us, L1 ~69%, DRAM ~43%).
// ---------------------------------------------------------------------------

#define P2 3481u
#define Q2 3721u
#define NN 3599u
#define N2 12952801u
#define MU 1119u
#define INV_P2_MOD_Q2 1876u

__device__ uint32_t g_Ptab[3481];   // pc = r_p + P2*bq  (< n^2 < 2^24)
__device__ uint16_t g_Atab[3721];   // a  = r_q * 1876 mod Q2
__device__ int g_mode;              // 0=int64, 1=int32, 2=float32, 3=double

template <uint32_t MOD>
__device__ __forceinline__ uint32_t powmod_lambda(uint32_t b) {
    // exponent 1740 = 0b11011001100 (11 bits); all products < 3721^2 < 2^24
    uint32_t r = 1u;
    uint32_t e = 1740u;
    #pragma unroll
    for (int i = 0; i < 11; i++) {
        if (e & 1u) r = (r * b) % MOD;
        b = (b * b) % MOD;
        e >>= 1u;
    }
    return r;
}

__global__ void setup_kernel(const uint32_t* __restrict__ w) {
    int i = blockIdx.x * blockDim.x + threadIdx.x;
    if (i < 3481) {
        uint32_t rp = powmod_lambda<P2>((uint32_t)i);
        uint32_t bq = (Q2 - (rp * INV_P2_MOD_Q2) % Q2) % Q2;
        g_Ptab[i] = rp + P2 * bq;            // folded: no mask/shift at use
    } else if (i < 3481 + 3721) {
        uint32_t y  = (uint32_t)(i - 3481);
        uint32_t aq = (powmod_lambda<Q2>(y) * INV_P2_MOD_Q2) % Q2;
        g_Atab[y] = (uint16_t)aq;
    } else if (i == 3481 + 3721) {
        // Layout probe: classify the input buffer's element encoding.
        bool odd_zero   = true;   // int64: high halves all 0
        bool all_small  = true;   // int32: every word < 2^24
        bool dbl_exp    = true;   // double: hi-word exponent in [0x3FF,0x416]
        bool even_low29 = true;   // double: integer<2^24 -> low 29 bits clear
        #pragma unroll
        for (int k = 0; k < 64; k++) {
            uint32_t v = w[k];
            if (k & 1) {
                if (v != 0u) odd_zero = false;
                uint32_t e = (v >> 20) & 0x7FFu;
                if (e < 0x3FFu || e > 0x416u) dbl_exp = false;
            } else {
                if (v & 0x1FFFFFFFu) even_low29 = false;
            }
            if (v >= 0x01000000u) all_small = false;
        }
        int mode;
        if (odd_zero)                   mode = 0;   // int64
        else if (all_small)             mode = 1;   // int32
        else if (dbl_exp && even_low29) mode = 3;   // double
        else                            mode = 2;   // float32
        g_mode = mode;
    }
}

template <bool RELU>
__device__ __forceinline__ float dec_one(uint32_t cv, const uint32_t* sP,
                                         const uint16_t* sA, float s) {
    uint32_t xp = cv % P2;
    uint32_t yq = cv % Q2;
    uint32_t pc = sP[xp];                  // r_p + P2*bq
    uint32_t a  = (uint32_t)sA[yq];
    uint32_t r  = pc + P2 * a;             // r = c^lambda mod n^2 (+ k*n^2) < 2^26
    uint32_t u  = r + (N2 - 1u);           // < 2^26 + 2^24, exact
    uint32_t q  = u / NN;                  // magic-number division
    uint32_t m  = (q * MU) % NN;           // k*n term vanishes mod n
    float f = (float)m * s;
    return RELU ? fmaxf(f, 0.0f) : f;      // m>=0: relu identity for s>=0
}

// Load 8 consecutive elements starting at element index o (multiple of 8).
template <int MODE>
__device__ __forceinline__ void load8(const void* in, uint32_t o, uint32_t cv[8]) {
    if (MODE == 1) {                        // int32
        uint4 a = __ldcs((const uint4*)in + (o >> 2));
        uint4 b = __ldcs((const uint4*)in + (o >> 2) + 1);
        cv[0]=a.x; cv[1]=a.y; cv[2]=a.z; cv[3]=a.w;
        cv[4]=b.x; cv[5]=b.y; cv[6]=b.z; cv[7]=b.w;
    } else if (MODE == 2) {                 // float32
        float4 a = __ldcs((const float4*)in + (o >> 2));
        float4 b = __ldcs((const float4*)in + (o >> 2) + 1);
        cv[0]=(uint32_t)a.x; cv[1]=(uint32_t)a.y; cv[2]=(uint32_t)a.z; cv[3]=(uint32_t)a.w;
        cv[4]=(uint32_t)b.x; cv[5]=(uint32_t)b.y; cv[6]=(uint32_t)b.z; cv[7]=(uint32_t)b.w;
    } else if (MODE == 0) {                 // int64 (values < 2^32 -> low words)
        const ulonglong2* p = (const ulonglong2*)in + (o >> 1);
        ulonglong2 a = __ldcs(p), b = __ldcs(p+1), c = __ldcs(p+2), d = __ldcs(p+3);
        cv[0]=(uint32_t)a.x; cv[1]=(uint32_t)a.y; cv[2]=(uint32_t)b.x; cv[3]=(uint32_t)b.y;
        cv[4]=(uint32_t)c.x; cv[5]=(uint32_t)c.y; cv[6]=(uint32_t)d.x; cv[7]=(uint32_t)d.y;
    } else {                                // double (integer-valued < 2^24)
        const double2* p = (const double2*)in + (o >> 1);
        double2 a = __ldcs(p), b = __ldcs(p+1), c = __ldcs(p+2), d = __ldcs(p+3);
        cv[0]=(uint32_t)__double2ll_rn(a.x); cv[1]=(uint32_t)__double2ll_rn(a.y);
        cv[2]=(uint32_t)__double2ll_rn(b.x); cv[3]=(uint32_t)__double2ll_rn(b.y);
        cv[4]=(uint32_t)__double2ll_rn(c.x); cv[5]=(uint32_t)__double2ll_rn(c.y);
        cv[6]=(uint32_t)__double2ll_rn(d.x); cv[7]=(uint32_t)__double2ll_rn(d.y);
    }
}

template <int MODE, bool RELU>
__device__ __forceinline__ void run_loop(const void* in, float* out, uint32_t n,
                                         const uint32_t* sP, const uint16_t* sA,
                                         float s) {
    const uint32_t nocts  = n >> 3;
    const uint32_t stride = gridDim.x * blockDim.x;
    for (uint32_t g = blockIdx.x * blockDim.x + threadIdx.x;
         g < nocts; g += stride) {
        uint32_t o = g << 3;
        uint32_t cv[8];
        load8<MODE>(in, o, cv);
        float4 lo, hi;
        lo.x = dec_one<RELU>(cv[0], sP, sA, s);
        lo.y = dec_one<RELU>(cv[1], sP, sA, s);
        lo.z = dec_one<RELU>(cv[2], sP, sA, s);
        lo.w = dec_one<RELU>(cv[3], sP, sA, s);
        hi.x = dec_one<RELU>(cv[4], sP, sA, s);
        hi.y = dec_one<RELU>(cv[5], sP, sA, s);
        hi.z = dec_one<RELU>(cv[6], sP, sA, s);
        hi.w = dec_one<RELU>(cv[7], sP, sA, s);
        __stcs((float4*)out + (o >> 2),     lo);
        __stcs((float4*)out + (o >> 2) + 1, hi);
    }
    // Scalar tail (n % 8 != 0)
    uint32_t tail = nocts << 3;
    uint32_t ti = tail + blockIdx.x * blockDim.x + threadIdx.x;
    if (blockIdx.x == 0 && ti < n) {
        uint32_t cv;
        if (MODE == 0)      cv = (uint32_t)((const unsigned long long*)in)[ti];
        else if (MODE == 1) cv = ((const uint32_t*)in)[ti];
        else if (MODE == 2) cv = (uint32_t)((const float*)in)[ti];
        else                cv = (uint32_t)((const double*)in)[ti];
        out[ti] = dec_one<RELU>(cv, sP, sA, s);
    }
}

template <int MODE>
__device__ __forceinline__ void dispatch_relu(const void* in, float* out, uint32_t n,
                                              const uint32_t* sP, const uint16_t* sA,
                                              float s) {
    if (s >= 0.0f) run_loop<MODE, false>(in, out, n, sP, sA, s);
    else           run_loop<MODE, true >(in, out, n, sP, sA, s);
}

__global__ __launch_bounds__(256) void paillier_dec_kernel(
    const void* __restrict__ in,
    const float* __restrict__ inv_scale,
    float* __restrict__ out,
    uint32_t n)
{
    __shared__ uint32_t sP[3481];
    __shared__ uint16_t sA[3721];
    for (int i = threadIdx.x; i < 3481; i += 256) sP[i] = g_Ptab[i];
    for (int i = threadIdx.x; i < 3721; i += 256) sA[i] = g_Atab[i];
    __syncthreads();

    const float s = inv_scale[0] / 1000.0f;
    switch (g_mode) {                      // uniform across the grid
        case 0: dispatch_relu<0>(in, out, n, sP, sA, s); break;
        case 1: dispatch_relu<1>(in, out, n, sP, sA, s); break;
        case 2: dispatch_relu<2>(in, out, n, sP, sA, s); break;
        default: dispatch_relu<3>(in, out, n, sP, sA, s); break;
    }
}

extern "C" void kernel_launch(void* const* d_in, const int* in_sizes, int n_in,
                              void* d_out, int out_size) {
    // Identify inputs by size: ciphertext tensor is huge, inv_scale is 1 elem.
    int ci = 0, si = 1;
    if (n_in >= 2 && in_sizes[0] <= 1) { ci = 1; si = 0; }
    const void* c        = d_in[ci];
    const float* inv_scl = (const float*)d_in[si];
    float* out           = (float*)d_out;
    uint32_t n = (uint32_t)out_size;   // output element count is unambiguous

    setup_kernel<<<(3481 + 3721 + 1 + 255) / 256, 256>>>((const uint32_t*)c);

    // Persistent: 148 SMs x 8 blocks x 256 threads (64 warps/SM, 32 regs =
    // exactly the regfile limit for full occupancy).
    paillier_dec_kernel<<<148 * 8, 256>>>(c, inv_scl, out, n);
}